// round 1
// baseline (speedup 1.0000x reference)
#include <cuda_runtime.h>
#include <math.h>

#define N_NODES   50000
#define N_EDGES   800000
#define E_TOT     (N_EDGES + N_NODES)
#define D_IN      128
#define HEADS     8
#define CDIM      32
#define HIDDEN    256
#define NEG_SLOPE 0.2f

// ---------------- device scratch (allocation-free rule: __device__ globals) ---------
__device__ __align__(128) float g_h    [N_NODES * HIDDEN];   // 51.2 MB  x@W
__device__ __align__(128) float g_out  [N_NODES * HIDDEN];   // 51.2 MB  aggregated
__device__ __align__(128) float g_asrc [N_NODES * HEADS];
__device__ __align__(128) float g_adst [N_NODES * HEADS];
__device__ __align__(128) float g_denom[N_NODES * HEADS];
__device__ __align__(128) float g_pooled[HIDDEN];

// vector float reduction (sm_90+): 4 floats per L2 atomic op
__device__ __forceinline__ void red_add_v4(float* addr, float4 v) {
    asm volatile("red.global.add.v4.f32 [%0], {%1,%2,%3,%4};"
                 :: "l"(addr), "f"(v.x), "f"(v.y), "f"(v.z), "f"(v.w)
                 : "memory");
}

// ---------------- K0: zero scratch --------------------------------------------------
#define NH4 (N_NODES * HIDDEN / 4)   // 3,200,000
#define ND4 (N_NODES * HEADS / 4)    // 100,000
__global__ __launch_bounds__(256) void k_zero() {
    int i = blockIdx.x * 256 + threadIdx.x;
    float4 z = make_float4(0.f, 0.f, 0.f, 0.f);
    if (i < NH4) ((float4*)g_out)[i]   = z;
    if (i < ND4) ((float4*)g_denom)[i] = z;
    if (i < HIDDEN / 4) ((float4*)g_pooled)[i] = z;
}

// ---------------- K1: h = x @ W  (fp32 tiled GEMM, 128x64 tile, 8x4 microtile) ------
#define BM 128
#define BN 64
#define BK 32
#define XS_STRIDE 132   // 128 + 4 pad, 16B-multiple
#define WS_STRIDE 68    // 64 + 4 pad, 16B-multiple

__global__ __launch_bounds__(256) void k_gemm(const float* __restrict__ x,
                                              const float* __restrict__ W) {
    __shared__ __align__(16) float xs[BK * XS_STRIDE];  // [k][m]
    __shared__ __align__(16) float ws[BK * WS_STRIDE];  // [k][n]
    const int t     = threadIdx.x;
    const int mBase = blockIdx.x * BM;
    const int nBase = blockIdx.y * BN;
    const int tx    = t & 15;    // 16 col groups  -> 4 cols each
    const int ty    = t >> 4;    // 16 row groups  -> 8 rows each

    float acc[8][4];
#pragma unroll
    for (int i = 0; i < 8; i++)
#pragma unroll
        for (int j = 0; j < 4; j++) acc[i][j] = 0.f;

    for (int kBase = 0; kBase < D_IN; kBase += BK) {
        // load x tile (transpose into xs[k][m]); 4 float4 per thread
#pragma unroll
        for (int p = 0; p < 4; p++) {
            int id   = t + p * 256;
            int row  = id >> 3;      // 0..127
            int quad = id & 7;       // 0..7
            int m    = mBase + row;
            float4 v = make_float4(0.f, 0.f, 0.f, 0.f);
            if (m < N_NODES)
                v = *(const float4*)(x + (size_t)m * D_IN + kBase + quad * 4);
            int k = quad * 4;
            xs[(k + 0) * XS_STRIDE + row] = v.x;
            xs[(k + 1) * XS_STRIDE + row] = v.y;
            xs[(k + 2) * XS_STRIDE + row] = v.z;
            xs[(k + 3) * XS_STRIDE + row] = v.w;
        }
        // load W tile; 2 float4 per thread
#pragma unroll
        for (int p = 0; p < 2; p++) {
            int id   = t + p * 256;
            int kr   = id >> 4;      // 0..31
            int quad = id & 15;      // 0..15
            float4 v = *(const float4*)(W + (size_t)(kBase + kr) * HIDDEN + nBase + quad * 4);
            *(float4*)(ws + kr * WS_STRIDE + quad * 4) = v;
        }
        __syncthreads();

#pragma unroll
        for (int kk = 0; kk < BK; kk++) {
            float4 x0 = *(const float4*)(xs + kk * XS_STRIDE + ty * 8);
            float4 x1 = *(const float4*)(xs + kk * XS_STRIDE + ty * 8 + 4);
            float4 wv = *(const float4*)(ws + kk * WS_STRIDE + tx * 4);
            float xr[8] = {x0.x, x0.y, x0.z, x0.w, x1.x, x1.y, x1.z, x1.w};
            float wc[4] = {wv.x, wv.y, wv.z, wv.w};
#pragma unroll
            for (int i = 0; i < 8; i++)
#pragma unroll
                for (int j = 0; j < 4; j++) acc[i][j] = fmaf(xr[i], wc[j], acc[i][j]);
        }
        __syncthreads();
    }

#pragma unroll
    for (int i = 0; i < 8; i++) {
        int m = mBase + ty * 8 + i;
        if (m < N_NODES) {
            float4 v = make_float4(acc[i][0], acc[i][1], acc[i][2], acc[i][3]);
            *(float4*)(g_h + (size_t)m * HIDDEN + nBase + tx * 4) = v;
        }
    }
}

// ---------------- K1b: per-node attention logits ------------------------------------
__global__ __launch_bounds__(256) void k_att(const float* __restrict__ att_src,
                                             const float* __restrict__ att_dst) {
    int idx = blockIdx.x * 256 + threadIdx.x;
    if (idx >= N_NODES * HEADS) return;
    int n = idx >> 3, hd = idx & 7;
    const float4* hp = (const float4*)(g_h + (size_t)n * HIDDEN + hd * CDIM);
    const float4* ap = (const float4*)(att_src + hd * CDIM);
    const float4* bp = (const float4*)(att_dst + hd * CDIM);
    float ss = 0.f, sd = 0.f;
#pragma unroll
    for (int i = 0; i < 8; i++) {
        float4 hv = hp[i], av = ap[i], bv = bp[i];
        ss += hv.x * av.x + hv.y * av.y + hv.z * av.z + hv.w * av.w;
        sd += hv.x * bv.x + hv.y * bv.y + hv.z * bv.z + hv.w * bv.w;
    }
    g_asrc[idx] = ss;
    g_adst[idx] = sd;
}

// ---------------- K2: softmax denominators (max-shift skipped: shift-invariant) -----
__device__ __forceinline__ float leaky_exp(float v) {
    return expf(v > 0.f ? v : NEG_SLOPE * v);
}

__global__ __launch_bounds__(256) void k_denom(const int* __restrict__ ei) {
    int e = blockIdx.x * 256 + threadIdx.x;
    if (e >= E_TOT) return;
    int s, d;
    if (e < N_EDGES) { s = ei[e]; d = ei[N_EDGES + e]; }
    else             { s = d = e - N_EDGES; }
    const float4* as = (const float4*)(g_asrc + s * 8);
    const float4* ad = (const float4*)(g_adst + d * 8);
    float4 a0 = as[0], a1 = as[1], b0 = ad[0], b1 = ad[1];
    float4 e0, e1;
    e0.x = leaky_exp(a0.x + b0.x); e0.y = leaky_exp(a0.y + b0.y);
    e0.z = leaky_exp(a0.z + b0.z); e0.w = leaky_exp(a0.w + b0.w);
    e1.x = leaky_exp(a1.x + b1.x); e1.y = leaky_exp(a1.y + b1.y);
    e1.z = leaky_exp(a1.z + b1.z); e1.w = leaky_exp(a1.w + b1.w);
    red_add_v4(g_denom + d * 8,     e0);
    red_add_v4(g_denom + d * 8 + 4, e1);
}

// ---------------- K3: weighted aggregation (thread per edge-head) -------------------
__global__ __launch_bounds__(256) void k_aggr(const int* __restrict__ ei) {
    int idx = blockIdx.x * 256 + threadIdx.x;
    if (idx >= E_TOT * HEADS) return;
    int e = idx >> 3, hd = idx & 7;
    int s, d;
    if (e < N_EDGES) { s = ei[e]; d = ei[N_EDGES + e]; }
    else             { s = d = e - N_EDGES; }
    float v = g_asrc[s * 8 + hd] + g_adst[d * 8 + hd];
    v = v > 0.f ? v : NEG_SLOPE * v;
    float alpha = expf(v) / (g_denom[d * 8 + hd] + 1e-16f);

    const float4* hp = (const float4*)(g_h + (size_t)s * HIDDEN + hd * CDIM);
    float*        op = g_out + (size_t)d * HIDDEN + hd * CDIM;
#pragma unroll
    for (int i = 0; i < 8; i++) {
        float4 hv = hp[i];
        float4 m  = make_float4(hv.x * alpha, hv.y * alpha, hv.z * alpha, hv.w * alpha);
        red_add_v4(op + i * 4, m);
    }
}

// ---------------- K4: bias + ELU + mean-pool ---------------------------------------
#define ROWS_PER_BLK 64
__global__ __launch_bounds__(256) void k_pool(const float* __restrict__ bias) {
    int col = threadIdx.x;
    int r0  = blockIdx.x * ROWS_PER_BLK;
    float b = bias[col];
    float acc = 0.f;
#pragma unroll 4
    for (int i = 0; i < ROWS_PER_BLK; i++) {
        int r = r0 + i;
        if (r < N_NODES) {
            float v = g_out[(size_t)r * HIDDEN + col] + b;
            acc += (v > 0.f) ? v : (expf(v) - 1.0f);   // ELU(alpha=1)
        }
    }
    atomicAdd(g_pooled + col, acc);
}

// ---------------- K5: MLP head (single block) --------------------------------------
__global__ __launch_bounds__(256) void k_mlp(const float* __restrict__ W1,
                                             const float* __restrict__ b1,
                                             const float* __restrict__ W2,
                                             const float* __restrict__ b2,
                                             float* __restrict__ out) {
    __shared__ float pm[HIDDEN];
    __shared__ float z[HIDDEN / 2];
    int t = threadIdx.x;
    pm[t] = g_pooled[t] * (1.0f / (float)N_NODES);
    __syncthreads();
    if (t < HIDDEN / 2) {
        float s = b1[t];
#pragma unroll 8
        for (int k = 0; k < HIDDEN; k++) s = fmaf(pm[k], W1[k * (HIDDEN / 2) + t], s);
        z[t] = fmaxf(s, 0.f);
    }
    __syncthreads();
    if (t < 6) {
        float s = b2[t];
#pragma unroll 8
        for (int j = 0; j < HIDDEN / 2; j++) s = fmaf(z[j], W2[j * 6 + t], s);
        out[t] = s;
    }
}

// ---------------- launch -----------------------------------------------------------
extern "C" void kernel_launch(void* const* d_in, const int* in_sizes, int n_in,
                              void* d_out, int out_size) {
    const float* x       = (const float*)d_in[0];
    const int*   ei      = (const int*)  d_in[1];
    const float* W       = (const float*)d_in[2];
    const float* att_src = (const float*)d_in[3];
    const float* att_dst = (const float*)d_in[4];
    const float* bias    = (const float*)d_in[5];
    const float* W1      = (const float*)d_in[6];
    const float* b1      = (const float*)d_in[7];
    const float* W2      = (const float*)d_in[8];
    const float* b2      = (const float*)d_in[9];
    float* out = (float*)d_out;

    k_zero<<<(NH4 + 255) / 256, 256>>>();

    dim3 g1((N_NODES + BM - 1) / BM, HIDDEN / BN);   // 391 x 4
    k_gemm<<<g1, 256>>>(x, W);

    k_att<<<(N_NODES * HEADS + 255) / 256, 256>>>(att_src, att_dst);

    k_denom<<<(E_TOT + 255) / 256, 256>>>(ei);

    k_aggr<<<((long)E_TOT * HEADS + 255) / 256, 256>>>(ei);

    k_pool<<<(N_NODES + ROWS_PER_BLK - 1) / ROWS_PER_BLK, 256>>>(bias);

    k_mlp<<<1, 256>>>(W1, b1, W2, b2, out);
}

// round 2
// speedup vs baseline: 1.7190x; 1.7190x over previous
#include <cuda_runtime.h>
#include <math.h>

#define N_NODES   50000
#define N_EDGES   800000
#define E_TOT     (N_EDGES + N_NODES)
#define D_IN      128
#define HEADS     8
#define CDIM      32
#define HIDDEN    256
#define NEG_SLOPE 0.2f

// ---------------- device scratch (allocation-free rule: __device__ globals) ---------
__device__ __align__(128) float g_h    [N_NODES * HIDDEN];   // 51.2 MB  x@W
__device__ __align__(128) float g_asrc [N_NODES * HEADS];
__device__ __align__(128) float g_adst [N_NODES * HEADS];
__device__ __align__(128) float g_pooled[HIDDEN];
__device__ __align__(128) int   g_hist [N_NODES];            // in-degree
__device__ __align__(128) int   g_ptr  [N_NODES + 1];        // CSR row ptr
__device__ __align__(128) int   g_cur  [N_NODES];            // scatter cursor
__device__ __align__(128) int   g_csr_src[E_TOT];            // 3.4 MB

__device__ __forceinline__ void red_add_f32(float* addr, float v) {
    asm volatile("red.global.add.f32 [%0], %1;" :: "l"(addr), "f"(v) : "memory");
}

// ---------------- K0: zero hist + pooled -------------------------------------------
__global__ __launch_bounds__(256) void k_init() {
    int i = blockIdx.x * 256 + threadIdx.x;
    if (i < N_NODES) g_hist[i] = 0;
    if (i < HIDDEN)  g_pooled[i] = 0.f;
}

// ---------------- K1: h = x @ W  (fp32 tiled GEMM, 128x64 tile, 8x4 microtile) ------
#define BM 128
#define BN 64
#define BK 32
#define XS_STRIDE 132
#define WS_STRIDE 68

__global__ __launch_bounds__(256) void k_gemm(const float* __restrict__ x,
                                              const float* __restrict__ W) {
    __shared__ __align__(16) float xs[BK * XS_STRIDE];  // [k][m]
    __shared__ __align__(16) float ws[BK * WS_STRIDE];  // [k][n]
    const int t     = threadIdx.x;
    const int mBase = blockIdx.x * BM;
    const int nBase = blockIdx.y * BN;
    const int tx    = t & 15;
    const int ty    = t >> 4;

    float acc[8][4];
#pragma unroll
    for (int i = 0; i < 8; i++)
#pragma unroll
        for (int j = 0; j < 4; j++) acc[i][j] = 0.f;

    for (int kBase = 0; kBase < D_IN; kBase += BK) {
#pragma unroll
        for (int p = 0; p < 4; p++) {
            int id   = t + p * 256;
            int row  = id >> 3;
            int quad = id & 7;
            int m    = mBase + row;
            float4 v = make_float4(0.f, 0.f, 0.f, 0.f);
            if (m < N_NODES)
                v = *(const float4*)(x + (size_t)m * D_IN + kBase + quad * 4);
            int k = quad * 4;
            xs[(k + 0) * XS_STRIDE + row] = v.x;
            xs[(k + 1) * XS_STRIDE + row] = v.y;
            xs[(k + 2) * XS_STRIDE + row] = v.z;
            xs[(k + 3) * XS_STRIDE + row] = v.w;
        }
#pragma unroll
        for (int p = 0; p < 2; p++) {
            int id   = t + p * 256;
            int kr   = id >> 4;
            int quad = id & 15;
            float4 v = *(const float4*)(W + (size_t)(kBase + kr) * HIDDEN + nBase + quad * 4);
            *(float4*)(ws + kr * WS_STRIDE + quad * 4) = v;
        }
        __syncthreads();

#pragma unroll
        for (int kk = 0; kk < BK; kk++) {
            float4 x0 = *(const float4*)(xs + kk * XS_STRIDE + ty * 8);
            float4 x1 = *(const float4*)(xs + kk * XS_STRIDE + ty * 8 + 4);
            float4 wv = *(const float4*)(ws + kk * WS_STRIDE + tx * 4);
            float xr[8] = {x0.x, x0.y, x0.z, x0.w, x1.x, x1.y, x1.z, x1.w};
            float wc[4] = {wv.x, wv.y, wv.z, wv.w};
#pragma unroll
            for (int i = 0; i < 8; i++)
#pragma unroll
                for (int j = 0; j < 4; j++) acc[i][j] = fmaf(xr[i], wc[j], acc[i][j]);
        }
        __syncthreads();
    }

#pragma unroll
    for (int i = 0; i < 8; i++) {
        int m = mBase + ty * 8 + i;
        if (m < N_NODES) {
            float4 v = make_float4(acc[i][0], acc[i][1], acc[i][2], acc[i][3]);
            *(float4*)(g_h + (size_t)m * HIDDEN + nBase + tx * 4) = v;
        }
    }
}

// ---------------- K2: per-node attention logits -------------------------------------
__global__ __launch_bounds__(256) void k_att(const float* __restrict__ att_src,
                                             const float* __restrict__ att_dst) {
    int idx = blockIdx.x * 256 + threadIdx.x;
    if (idx >= N_NODES * HEADS) return;
    int n = idx >> 3, hd = idx & 7;
    const float4* hp = (const float4*)(g_h + (size_t)n * HIDDEN + hd * CDIM);
    const float4* ap = (const float4*)(att_src + hd * CDIM);
    const float4* bp = (const float4*)(att_dst + hd * CDIM);
    float ss = 0.f, sd = 0.f;
#pragma unroll
    for (int i = 0; i < 8; i++) {
        float4 hv = hp[i], av = ap[i], bv = bp[i];
        ss += hv.x * av.x + hv.y * av.y + hv.z * av.z + hv.w * av.w;
        sd += hv.x * bv.x + hv.y * bv.y + hv.z * bv.z + hv.w * bv.w;
    }
    g_asrc[idx] = ss;
    g_adst[idx] = sd;
}

// ---------------- K3: in-degree histogram -------------------------------------------
__global__ __launch_bounds__(256) void k_hist(const int* __restrict__ ei) {
    int e = blockIdx.x * 256 + threadIdx.x;
    if (e >= E_TOT) return;
    int d = (e < N_EDGES) ? ei[N_EDGES + e] : (e - N_EDGES);
    atomicAdd(&g_hist[d], 1);
}

// ---------------- K4: single-block exclusive scan over 50k counters -----------------
#define SCAN_T 1024
__global__ __launch_bounds__(SCAN_T) void k_scan() {
    __shared__ int sm[SCAN_T];
    const int t = threadIdx.x;
    const int chunk = (N_NODES + SCAN_T - 1) / SCAN_T;  // 49
    const int beg = t * chunk;
    int sum = 0;
    for (int i = 0; i < chunk; i++) {
        int idx = beg + i;
        if (idx < N_NODES) sum += g_hist[idx];
    }
    sm[t] = sum;
    __syncthreads();
    // Hillis-Steele inclusive scan
    for (int ofs = 1; ofs < SCAN_T; ofs <<= 1) {
        int v = (t >= ofs) ? sm[t - ofs] : 0;
        __syncthreads();
        sm[t] += v;
        __syncthreads();
    }
    int base = sm[t] - sum;  // exclusive
    int run = base;
    for (int i = 0; i < chunk; i++) {
        int idx = beg + i;
        if (idx < N_NODES) {
            g_ptr[idx] = run;
            g_cur[idx] = run;
            run += g_hist[idx];
        }
    }
    if (t == SCAN_T - 1) g_ptr[N_NODES] = E_TOT;
}

// ---------------- K5: scatter edges into CSR ----------------------------------------
__global__ __launch_bounds__(256) void k_scatter(const int* __restrict__ ei) {
    int e = blockIdx.x * 256 + threadIdx.x;
    if (e >= E_TOT) return;
    int s, d;
    if (e < N_EDGES) { s = ei[e]; d = ei[N_EDGES + e]; }
    else             { s = d = e - N_EDGES; }
    int pos = atomicAdd(&g_cur[d], 1);
    g_csr_src[pos] = s;
}

// ---------------- K6: warp-per-node softmax aggregation + bias+ELU+mean-pool --------
#define AGGR_BLOCKS 1184
__global__ __launch_bounds__(256) void k_aggr(const float* __restrict__ bias) {
    const int lane   = threadIdx.x & 31;
    const int warpId = threadIdx.x >> 5;
    const int gw     = blockIdx.x * 8 + warpId;
    const int nWarps = AGGR_BLOCKS * 8;

    // per-lane constants: bias for columns j*32+lane
    float bl[8];
#pragma unroll
    for (int j = 0; j < 8; j++) bl[j] = bias[j * 32 + lane];

    float pool[8];
#pragma unroll
    for (int j = 0; j < 8; j++) pool[j] = 0.f;

    for (int n = gw; n < N_NODES; n += nWarps) {
        const int beg = g_ptr[n];
        const int end = g_ptr[n + 1];
        const float adst = (lane < 8) ? g_adst[n * 8 + lane] : 0.f;

        float acc[8];
#pragma unroll
        for (int j = 0; j < 8; j++) acc[j] = 0.f;
        float tsum = 0.f;  // lanes 0..7: per-head exp-sum

        for (int idx = beg; idx < end; idx++) {
            const int s = g_csr_src[idx];    // lane-uniform -> broadcast load
            float t = 0.f;
            if (lane < 8) {
                float v = g_asrc[s * 8 + lane] + adst;
                v = (v > 0.f) ? v : NEG_SLOPE * v;
                t = __expf(v);
                tsum += t;
            }
            const float* hrow = g_h + (size_t)s * HIDDEN + lane;
#pragma unroll
            for (int j = 0; j < 8; j++) {
                float aj = __shfl_sync(0xffffffffu, t, j);
                acc[j] = fmaf(aj, hrow[j * 32], acc[j]);
            }
        }
        // epilogue: divide by denom, +bias, ELU, pool
#pragma unroll
        for (int j = 0; j < 8; j++) {
            float denom = __shfl_sync(0xffffffffu, tsum, j);
            float o = acc[j] / (denom + 1e-16f) + bl[j];
            o = (o > 0.f) ? o : (__expf(o) - 1.0f);
            pool[j] += o;
        }
    }
    // flush pool partials
#pragma unroll
    for (int j = 0; j < 8; j++) red_add_f32(g_pooled + j * 32 + lane, pool[j]);
}

// ---------------- K7: MLP head (single block) --------------------------------------
__global__ __launch_bounds__(256) void k_mlp(const float* __restrict__ W1,
                                             const float* __restrict__ b1,
                                             const float* __restrict__ W2,
                                             const float* __restrict__ b2,
                                             float* __restrict__ out) {
    __shared__ float pm[HIDDEN];
    __shared__ float z[HIDDEN / 2];
    int t = threadIdx.x;
    pm[t] = g_pooled[t] * (1.0f / (float)N_NODES);
    __syncthreads();
    if (t < HIDDEN / 2) {
        float s = b1[t];
#pragma unroll 8
        for (int k = 0; k < HIDDEN; k++) s = fmaf(pm[k], W1[k * (HIDDEN / 2) + t], s);
        z[t] = fmaxf(s, 0.f);
    }
    __syncthreads();
    if (t < 6) {
        float s = b2[t];
#pragma unroll 8
        for (int j = 0; j < HIDDEN / 2; j++) s = fmaf(z[j], W2[j * 6 + t], s);
        out[t] = s;
    }
}

// ---------------- launch -----------------------------------------------------------
extern "C" void kernel_launch(void* const* d_in, const int* in_sizes, int n_in,
                              void* d_out, int out_size) {
    const float* x       = (const float*)d_in[0];
    const int*   ei      = (const int*)  d_in[1];
    const float* W       = (const float*)d_in[2];
    const float* att_src = (const float*)d_in[3];
    const float* att_dst = (const float*)d_in[4];
    const float* bias    = (const float*)d_in[5];
    const float* W1      = (const float*)d_in[6];
    const float* b1      = (const float*)d_in[7];
    const float* W2      = (const float*)d_in[8];
    const float* b2      = (const float*)d_in[9];
    float* out = (float*)d_out;

    k_init<<<(N_NODES + 255) / 256, 256>>>();

    dim3 g1((N_NODES + BM - 1) / BM, HIDDEN / BN);   // 391 x 4
    k_gemm<<<g1, 256>>>(x, W);

    k_att<<<(N_NODES * HEADS + 255) / 256, 256>>>(att_src, att_dst);

    k_hist<<<(E_TOT + 255) / 256, 256>>>(ei);
    k_scan<<<1, SCAN_T>>>();
    k_scatter<<<(E_TOT + 255) / 256, 256>>>(ei);

    k_aggr<<<AGGR_BLOCKS, 256>>>(bias);

    k_mlp<<<1, 256>>>(W1, b1, W2, b2, out);
}

// round 3
// speedup vs baseline: 1.8992x; 1.1048x over previous
#include <cuda_runtime.h>
#include <cuda_bf16.h>
#include <math.h>

#define N_NODES   50000
#define N_EDGES   800000
#define E_TOT     (N_EDGES + N_NODES)
#define D_IN      128
#define HEADS     8
#define CDIM      32
#define HIDDEN    256
#define NEG_SLOPE 0.2f

// ---------------- device scratch ---------------------------------------------------
__device__ __align__(128) __nv_bfloat16 g_hb[N_NODES * HIDDEN];  // 25.6 MB  x@W (bf16)
__device__ __align__(128) float g_asrc [N_NODES * HEADS];
__device__ __align__(128) float g_adst [N_NODES * HEADS];
__device__ __align__(128) float g_pooled[HIDDEN];
__device__ __align__(128) int   g_hist [N_NODES];
__device__ __align__(128) int   g_ptr  [N_NODES + 1];
__device__ __align__(128) int   g_cur  [N_NODES];
__device__ __align__(128) int   g_csr_src[E_TOT];

__device__ __forceinline__ void red_add_v2(float* addr, float a, float b) {
    asm volatile("red.global.add.v2.f32 [%0], {%1,%2};"
                 :: "l"(addr), "f"(a), "f"(b) : "memory");
}

// ---------------- K0: zero hist + pooled -------------------------------------------
__global__ __launch_bounds__(256) void k_init() {
    int i = blockIdx.x * 256 + threadIdx.x;
    if (i < N_NODES) g_hist[i] = 0;
    if (i < HIDDEN)  g_pooled[i] = 0.f;
}

// ---------------- K1: h = x @ W  (fp32 128x128 tile, 8x8 microtile, bf16 out) -------
#define BM 128
#define BN 128
#define BK 16
#define XS_STRIDE 132
#define WS_STRIDE 132

__global__ __launch_bounds__(256) void k_gemm(const float* __restrict__ x,
                                              const float* __restrict__ W) {
    __shared__ __align__(16) float xs[BK * XS_STRIDE];  // [k][m]
    __shared__ __align__(16) float ws[BK * WS_STRIDE];  // [k][n]
    const int t     = threadIdx.x;
    const int mBase = blockIdx.x * BM;
    const int nBase = blockIdx.y * BN;
    const int tx    = t & 15;   // 16 -> 8 cols each
    const int ty    = t >> 4;   // 16 -> 8 rows each

    float acc[8][8];
#pragma unroll
    for (int i = 0; i < 8; i++)
#pragma unroll
        for (int j = 0; j < 8; j++) acc[i][j] = 0.f;

    for (int kBase = 0; kBase < D_IN; kBase += BK) {
        // x tile: 128 rows x 16 k = 512 float4; 2 per thread, transpose into xs[k][m]
#pragma unroll
        for (int p = 0; p < 2; p++) {
            int id   = t + p * 256;
            int row  = id >> 2;      // 0..127
            int quad = id & 3;       // 0..3 -> k offset quad*4
            int m    = mBase + row;
            float4 v = make_float4(0.f, 0.f, 0.f, 0.f);
            if (m < N_NODES)
                v = *(const float4*)(x + (size_t)m * D_IN + kBase + quad * 4);
            int k = quad * 4;
            xs[(k + 0) * XS_STRIDE + row] = v.x;
            xs[(k + 1) * XS_STRIDE + row] = v.y;
            xs[(k + 2) * XS_STRIDE + row] = v.z;
            xs[(k + 3) * XS_STRIDE + row] = v.w;
        }
        // W tile: 16 k x 128 n = 512 float4; 2 per thread
#pragma unroll
        for (int p = 0; p < 2; p++) {
            int id = t + p * 256;
            int kr = id >> 5;        // 0..15
            int c  = (id & 31) * 4;  // 0..124
            float4 v = *(const float4*)(W + (size_t)(kBase + kr) * HIDDEN + nBase + c);
            *(float4*)(ws + kr * WS_STRIDE + c) = v;
        }
        __syncthreads();

#pragma unroll
        for (int kk = 0; kk < BK; kk++) {
            float4 x0 = *(const float4*)(xs + kk * XS_STRIDE + ty * 8);
            float4 x1 = *(const float4*)(xs + kk * XS_STRIDE + ty * 8 + 4);
            float4 w0 = *(const float4*)(ws + kk * WS_STRIDE + tx * 8);
            float4 w1 = *(const float4*)(ws + kk * WS_STRIDE + tx * 8 + 4);
            float xr[8] = {x0.x, x0.y, x0.z, x0.w, x1.x, x1.y, x1.z, x1.w};
            float wc[8] = {w0.x, w0.y, w0.z, w0.w, w1.x, w1.y, w1.z, w1.w};
#pragma unroll
            for (int i = 0; i < 8; i++)
#pragma unroll
                for (int j = 0; j < 8; j++) acc[i][j] = fmaf(xr[i], wc[j], acc[i][j]);
        }
        __syncthreads();
    }

#pragma unroll
    for (int i = 0; i < 8; i++) {
        int m = mBase + ty * 8 + i;
        if (m < N_NODES) {
            __nv_bfloat162 b0 = __floats2bfloat162_rn(acc[i][0], acc[i][1]);
            __nv_bfloat162 b1 = __floats2bfloat162_rn(acc[i][2], acc[i][3]);
            __nv_bfloat162 b2 = __floats2bfloat162_rn(acc[i][4], acc[i][5]);
            __nv_bfloat162 b3 = __floats2bfloat162_rn(acc[i][6], acc[i][7]);
            uint4 pack;
            pack.x = *(unsigned*)&b0; pack.y = *(unsigned*)&b1;
            pack.z = *(unsigned*)&b2; pack.w = *(unsigned*)&b3;
            *(uint4*)(g_hb + (size_t)m * HIDDEN + nBase + tx * 8) = pack;
        }
    }
}

// ---------------- K2: per-node attention logits (bf16 h) ----------------------------
__global__ __launch_bounds__(256) void k_att(const float* __restrict__ att_src,
                                             const float* __restrict__ att_dst) {
    int idx = blockIdx.x * 256 + threadIdx.x;
    if (idx >= N_NODES * HEADS) return;
    int n = idx >> 3, hd = idx & 7;
    const __nv_bfloat162* hp = (const __nv_bfloat162*)(g_hb + (size_t)n * HIDDEN + hd * CDIM);
    const float* ap = att_src + hd * CDIM;
    const float* bp = att_dst + hd * CDIM;
    float ss = 0.f, sd = 0.f;
#pragma unroll
    for (int i = 0; i < 16; i++) {
        float2 hv = __bfloat1622float2(hp[i]);
        ss += hv.x * ap[2 * i] + hv.y * ap[2 * i + 1];
        sd += hv.x * bp[2 * i] + hv.y * bp[2 * i + 1];
    }
    g_asrc[idx] = ss;
    g_adst[idx] = sd;
}

// ---------------- K3: in-degree histogram -------------------------------------------
__global__ __launch_bounds__(256) void k_hist(const int* __restrict__ ei) {
    int e = blockIdx.x * 256 + threadIdx.x;
    if (e >= E_TOT) return;
    int d = (e < N_EDGES) ? ei[N_EDGES + e] : (e - N_EDGES);
    atomicAdd(&g_hist[d], 1);
}

// ---------------- K4: single-block exclusive scan -----------------------------------
#define SCAN_T 1024
__global__ __launch_bounds__(SCAN_T) void k_scan() {
    __shared__ int sm[SCAN_T];
    const int t = threadIdx.x;
    const int chunk = (N_NODES + SCAN_T - 1) / SCAN_T;
    const int beg = t * chunk;
    int sum = 0;
    for (int i = 0; i < chunk; i++) {
        int idx = beg + i;
        if (idx < N_NODES) sum += g_hist[idx];
    }
    sm[t] = sum;
    __syncthreads();
    for (int ofs = 1; ofs < SCAN_T; ofs <<= 1) {
        int v = (t >= ofs) ? sm[t - ofs] : 0;
        __syncthreads();
        sm[t] += v;
        __syncthreads();
    }
    int run = sm[t] - sum;
    for (int i = 0; i < chunk; i++) {
        int idx = beg + i;
        if (idx < N_NODES) {
            g_ptr[idx] = run;
            g_cur[idx] = run;
            run += g_hist[idx];
        }
    }
    if (t == SCAN_T - 1) g_ptr[N_NODES] = E_TOT;
}

// ---------------- K5: scatter edges into CSR ----------------------------------------
__global__ __launch_bounds__(256) void k_scatter(const int* __restrict__ ei) {
    int e = blockIdx.x * 256 + threadIdx.x;
    if (e >= E_TOT) return;
    int s, d;
    if (e < N_EDGES) { s = ei[e]; d = ei[N_EDGES + e]; }
    else             { s = d = e - N_EDGES; }
    int pos = atomicAdd(&g_cur[d], 1);
    g_csr_src[pos] = s;
}

// ---------------- K6: warp-per-node aggregation (bf16 gather) + ELU + pool ----------
#define AGGR_BLOCKS 1184
__global__ __launch_bounds__(256) void k_aggr(const float* __restrict__ bias) {
    const int lane   = threadIdx.x & 31;
    const int warpId = threadIdx.x >> 5;
    const int gw     = blockIdx.x * 8 + warpId;
    const int nWarps = AGGR_BLOCKS * 8;

    // lane handles column pairs p = lane + 32*j (cols 2p, 2p+1); head(p) = p>>4
    float2 bl[4], pool[4];
#pragma unroll
    for (int j = 0; j < 4; j++) {
        int p = lane + 32 * j;
        bl[j] = make_float2(bias[2 * p], bias[2 * p + 1]);
        pool[j] = make_float2(0.f, 0.f);
    }

    for (int n = gw; n < N_NODES; n += nWarps) {
        const int beg = g_ptr[n];
        const int end = g_ptr[n + 1];
        const float adst = (lane < 8) ? g_adst[n * 8 + lane] : 0.f;

        float2 acc[4];
#pragma unroll
        for (int j = 0; j < 4; j++) acc[j] = make_float2(0.f, 0.f);
        float tsum = 0.f;

        for (int base = beg; base < end; base += 32) {
            const int cnt = min(32, end - base);
            int sv = (base + lane < end) ? g_csr_src[base + lane] : 0;
            for (int e = 0; e < cnt; e++) {
                const int s = __shfl_sync(0xffffffffu, sv, e);
                float t = 0.f;
                if (lane < 8) {
                    float v = g_asrc[s * 8 + lane] + adst;
                    v = (v > 0.f) ? v : NEG_SLOPE * v;
                    t = __expf(v);
                    tsum += t;
                }
                const __nv_bfloat162* hrow =
                    (const __nv_bfloat162*)(g_hb + (size_t)s * HIDDEN);
#pragma unroll
                for (int j = 0; j < 4; j++) {
                    __nv_bfloat162 hv = hrow[lane + 32 * j];
                    float aj = __shfl_sync(0xffffffffu, t, (lane >> 4) + 2 * j);
                    float2 f = __bfloat1622float2(hv);
                    acc[j].x = fmaf(aj, f.x, acc[j].x);
                    acc[j].y = fmaf(aj, f.y, acc[j].y);
                }
            }
        }
#pragma unroll
        for (int j = 0; j < 4; j++) {
            float denom = __shfl_sync(0xffffffffu, tsum, (lane >> 4) + 2 * j);
            float inv = 1.0f / (denom + 1e-16f);
            float ox = acc[j].x * inv + bl[j].x;
            float oy = acc[j].y * inv + bl[j].y;
            ox = (ox > 0.f) ? ox : (__expf(ox) - 1.0f);
            oy = (oy > 0.f) ? oy : (__expf(oy) - 1.0f);
            pool[j].x += ox;
            pool[j].y += oy;
        }
    }
#pragma unroll
    for (int j = 0; j < 4; j++) {
        int p = lane + 32 * j;
        red_add_v2(g_pooled + 2 * p, pool[j].x, pool[j].y);
    }
}

// ---------------- K7: MLP head -----------------------------------------------------
__global__ __launch_bounds__(256) void k_mlp(const float* __restrict__ W1,
                                             const float* __restrict__ b1,
                                             const float* __restrict__ W2,
                                             const float* __restrict__ b2,
                                             float* __restrict__ out) {
    __shared__ float pm[HIDDEN];
    __shared__ float z[HIDDEN / 2];
    int t = threadIdx.x;
    pm[t] = g_pooled[t] * (1.0f / (float)N_NODES);
    __syncthreads();
    if (t < HIDDEN / 2) {
        float s = b1[t];
#pragma unroll 8
        for (int k = 0; k < HIDDEN; k++) s = fmaf(pm[k], W1[k * (HIDDEN / 2) + t], s);
        z[t] = fmaxf(s, 0.f);
    }
    __syncthreads();
    if (t < 6) {
        float s = b2[t];
#pragma unroll 8
        for (int j = 0; j < HIDDEN / 2; j++) s = fmaf(z[j], W2[j * 6 + t], s);
        out[t] = s;
    }
}

// ---------------- launch -----------------------------------------------------------
extern "C" void kernel_launch(void* const* d_in, const int* in_sizes, int n_in,
                              void* d_out, int out_size) {
    const float* x       = (const float*)d_in[0];
    const int*   ei      = (const int*)  d_in[1];
    const float* W       = (const float*)d_in[2];
    const float* att_src = (const float*)d_in[3];
    const float* att_dst = (const float*)d_in[4];
    const float* bias    = (const float*)d_in[5];
    const float* W1      = (const float*)d_in[6];
    const float* b1      = (const float*)d_in[7];
    const float* W2      = (const float*)d_in[8];
    const float* b2      = (const float*)d_in[9];
    float* out = (float*)d_out;

    k_init<<<(N_NODES + 255) / 256, 256>>>();

    dim3 g1((N_NODES + BM - 1) / BM, HIDDEN / BN);   // 391 x 2
    k_gemm<<<g1, 256>>>(x, W);

    k_att<<<(N_NODES * HEADS + 255) / 256, 256>>>(att_src, att_dst);

    k_hist<<<(E_TOT + 255) / 256, 256>>>(ei);
    k_scan<<<1, SCAN_T>>>();
    k_scatter<<<(E_TOT + 255) / 256, 256>>>(ei);

    k_aggr<<<AGGR_BLOCKS, 256>>>(bias);

    k_mlp<<<1, 256>>>(W1, b1, W2, b2, out);
}